// round 1
// baseline (speedup 1.0000x reference)
#include <cuda_runtime.h>
#include <cstdint>

#define BATCH 4
#define CIN   128
#define COUT  256
#define HW    1024
#define BK    16
#define BM    64    // o tile
#define BN    128   // p tile
#define NCHUNK (CIN / BK)

// ---- packed f32x2 helpers (Blackwell sm_100+) ----
__device__ __forceinline__ uint64_t bcast2(float v) {
    uint64_t r;
    asm("mov.b64 %0, {%1,%1};" : "=l"(r) : "f"(v));
    return r;
}
__device__ __forceinline__ void fma2(uint64_t& acc, uint64_t a, uint64_t b) {
    asm("fma.rn.f32x2 %0, %1, %2, %0;" : "+l"(acc) : "l"(a), "l"(b));
}
__device__ __forceinline__ float2 unpack2(uint64_t v) {
    float2 f;
    asm("mov.b64 {%0,%1}, %2;" : "=f"(f.x), "=f"(f.y) : "l"(v));
    return f;
}

__global__ __launch_bounds__(256, 1)
void pw_relu_gemm_kernel(const float* __restrict__ x,
                         const float* __restrict__ w,
                         float* __restrict__ out) {
    __shared__ float Xp[BK][BN];   // relu(x)
    __shared__ float Xm[BK][BN];   // relu(-x)
    __shared__ float Wp[BK][BM];   // relu(w), transposed [k][o]
    __shared__ float Wm[BK][BM];   // relu(-w)

    const int b  = blockIdx.z;
    const int o0 = blockIdx.y * BM;
    const int p0 = blockIdx.x * BN;
    const int tid = threadIdx.x;
    const int tx = tid & 15;   // p direction (16)
    const int ty = tid >> 4;   // o direction (16)

    const float* xb = x + (size_t)b * CIN * HW + p0;

    // X global-load mapping: 2048 floats/chunk = 512 float4; 2 per thread.
    const int xk0 = tid >> 5;          // k row 0..7 (second load: +8)
    const int xp4 = (tid & 31) * 4;    // float4 column within 128-wide p tile
    // W global-load mapping: 1024 floats/chunk = 256 float4; 1 per thread.
    const int wo  = tid >> 2;          // 0..63
    const int wk4 = (tid & 3) * 4;     // k sub-offset
    const float* wrow = w + (size_t)(o0 + wo) * CIN + wk4;

    uint64_t acc[4][4];                // [o micro][f32x2 group: pA0,pA1,pB0,pB1]
#pragma unroll
    for (int i = 0; i < 4; i++)
#pragma unroll
        for (int j = 0; j < 4; j++) acc[i][j] = 0ull;

    // prefetch chunk 0 into registers
    float4 xv0 = *(const float4*)(xb + (size_t)xk0 * HW + xp4);
    float4 xv1 = *(const float4*)(xb + (size_t)(xk0 + 8) * HW + xp4);
    float4 wv  = *(const float4*)(wrow);

    for (int kc = 0; kc < NCHUNK; kc++) {
        // ---- stage current chunk into smem with sign-split relu ----
        *(float4*)&Xp[xk0][xp4] = make_float4(fmaxf(xv0.x, 0.f), fmaxf(xv0.y, 0.f),
                                              fmaxf(xv0.z, 0.f), fmaxf(xv0.w, 0.f));
        *(float4*)&Xm[xk0][xp4] = make_float4(fmaxf(-xv0.x, 0.f), fmaxf(-xv0.y, 0.f),
                                              fmaxf(-xv0.z, 0.f), fmaxf(-xv0.w, 0.f));
        *(float4*)&Xp[xk0 + 8][xp4] = make_float4(fmaxf(xv1.x, 0.f), fmaxf(xv1.y, 0.f),
                                                  fmaxf(xv1.z, 0.f), fmaxf(xv1.w, 0.f));
        *(float4*)&Xm[xk0 + 8][xp4] = make_float4(fmaxf(-xv1.x, 0.f), fmaxf(-xv1.y, 0.f),
                                                  fmaxf(-xv1.z, 0.f), fmaxf(-xv1.w, 0.f));
        Wp[wk4 + 0][wo] = fmaxf(wv.x, 0.f);  Wm[wk4 + 0][wo] = fmaxf(-wv.x, 0.f);
        Wp[wk4 + 1][wo] = fmaxf(wv.y, 0.f);  Wm[wk4 + 1][wo] = fmaxf(-wv.y, 0.f);
        Wp[wk4 + 2][wo] = fmaxf(wv.z, 0.f);  Wm[wk4 + 2][wo] = fmaxf(-wv.z, 0.f);
        Wp[wk4 + 3][wo] = fmaxf(wv.w, 0.f);  Wm[wk4 + 3][wo] = fmaxf(-wv.w, 0.f);
        __syncthreads();

        // ---- prefetch next chunk (LDG latency hidden under compute) ----
        if (kc + 1 < NCHUNK) {
            const float* xc = xb + (size_t)(kc + 1) * BK * HW;
            xv0 = *(const float4*)(xc + (size_t)xk0 * HW + xp4);
            xv1 = *(const float4*)(xc + (size_t)(xk0 + 8) * HW + xp4);
            wv  = *(const float4*)(wrow + (kc + 1) * BK);
        }

        // ---- compute: 16 k-steps, 64 FMAs each via 32 fma.f32x2 ----
#pragma unroll
        for (int k = 0; k < BK; k++) {
            ulonglong2 xpa = *(const ulonglong2*)&Xp[k][tx * 4];
            ulonglong2 xpb = *(const ulonglong2*)&Xp[k][64 + tx * 4];
            ulonglong2 xma = *(const ulonglong2*)&Xm[k][tx * 4];
            ulonglong2 xmb = *(const ulonglong2*)&Xm[k][64 + tx * 4];
            float4 wp4 = *(const float4*)&Wp[k][ty * 4];
            float4 wm4 = *(const float4*)&Wm[k][ty * 4];
            float wpv[4] = {wp4.x, wp4.y, wp4.z, wp4.w};
            float wmv[4] = {wm4.x, wm4.y, wm4.z, wm4.w};
#pragma unroll
            for (int i = 0; i < 4; i++) {
                uint64_t wp2 = bcast2(wpv[i]);
                uint64_t wm2 = bcast2(wmv[i]);
                fma2(acc[i][0], wp2, xpa.x);
                fma2(acc[i][1], wp2, xpa.y);
                fma2(acc[i][2], wp2, xpb.x);
                fma2(acc[i][3], wp2, xpb.y);
                fma2(acc[i][0], wm2, xma.x);
                fma2(acc[i][1], wm2, xma.y);
                fma2(acc[i][2], wm2, xmb.x);
                fma2(acc[i][3], wm2, xmb.y);
            }
        }
        __syncthreads();
    }

    // ---- epilogue: coalesced float4 stores ----
    float* ob = out + ((size_t)b * COUT + o0 + ty * 4) * HW + p0 + tx * 4;
#pragma unroll
    for (int i = 0; i < 4; i++) {
        float2 a0 = unpack2(acc[i][0]);
        float2 a1 = unpack2(acc[i][1]);
        float2 a2 = unpack2(acc[i][2]);
        float2 a3 = unpack2(acc[i][3]);
        *(float4*)(ob + (size_t)i * HW)      = make_float4(a0.x, a0.y, a1.x, a1.y);
        *(float4*)(ob + (size_t)i * HW + 64) = make_float4(a2.x, a2.y, a3.x, a3.y);
    }
}

extern "C" void kernel_launch(void* const* d_in, const int* in_sizes, int n_in,
                              void* d_out, int out_size) {
    const float* x = (const float*)d_in[0];   // (4,128,32,32)
    const float* w = (const float*)d_in[1];   // (256*128,1,1,1)
    float* out = (float*)d_out;               // (4,256,32,32)
    dim3 grid(HW / BN, COUT / BM, BATCH);     // (8, 4, 4) = 128 blocks
    pw_relu_gemm_kernel<<<grid, 256>>>(x, w, out);
}

// round 3
// speedup vs baseline: 2.4466x; 2.4466x over previous
#include <cuda_runtime.h>
#include <cuda_bf16.h>
#include <cstdint>

#define BATCH 4
#define CIN   128
#define COUT  256
#define HW    1024
#define TILE_O 128
#define TILE_P 64
#define KEFF   256      // sign-split effective K
#define THREADS 256

// smem layout (bytes). Strides are 16B-multiples with (stride/4 mod 32) == 4
// so ldmatrix row addresses walk 4 banks per row -> conflict-free.
#define A_STRIDE 528    // 256 halves data + 8 halves pad
#define B_STRIDE 144    // 64 halves data + 8 halves pad
#define SMEM_A   0
#define SMEM_B   (TILE_O * A_STRIDE)              // 67584
#define SMEM_TOTAL (SMEM_B + KEFF * B_STRIDE)     // 104448

__device__ __forceinline__ uint32_t smem_u32(const void* p) {
    uint32_t a;
    asm("{ .reg .u64 t; cvta.to.shared.u64 t, %1; cvt.u32.u64 %0, t; }" : "=r"(a) : "l"(p));
    return a;
}
// pack two fp32 -> bf16x2, lo in lower half
__device__ __forceinline__ uint32_t pack_bf16x2(float lo, float hi) {
    uint32_t r;
    asm("cvt.rn.bf16x2.f32 %0, %1, %2;" : "=r"(r) : "f"(hi), "f"(lo));
    return r;
}
__device__ __forceinline__ void sts64(uint32_t addr, uint32_t a, uint32_t b) {
    asm volatile("st.shared.v2.b32 [%0], {%1,%2};" :: "r"(addr), "r"(a), "r"(b) : "memory");
}
__device__ __forceinline__ void sts128(uint32_t addr, uint4 v) {
    asm volatile("st.shared.v4.b32 [%0], {%1,%2,%3,%4};"
                 :: "r"(addr), "r"(v.x), "r"(v.y), "r"(v.z), "r"(v.w) : "memory");
}
__device__ __forceinline__ void ldsm_x4(uint32_t addr, uint32_t* r) {
    asm volatile("ldmatrix.sync.aligned.m8n8.x4.shared.b16 {%0,%1,%2,%3}, [%4];"
                 : "=r"(r[0]), "=r"(r[1]), "=r"(r[2]), "=r"(r[3]) : "r"(addr));
}
__device__ __forceinline__ void ldsm_x2_trans(uint32_t addr, uint32_t* r) {
    asm volatile("ldmatrix.sync.aligned.m8n8.x2.trans.shared.b16 {%0,%1}, [%2];"
                 : "=r"(r[0]), "=r"(r[1]) : "r"(addr));
}
__device__ __forceinline__ void mma_16816(float* c, const uint32_t* a, const uint32_t* b) {
    asm volatile(
        "mma.sync.aligned.m16n8k16.row.col.f32.bf16.bf16.f32 "
        "{%0,%1,%2,%3}, {%4,%5,%6,%7}, {%8,%9}, {%0,%1,%2,%3};"
        : "+f"(c[0]), "+f"(c[1]), "+f"(c[2]), "+f"(c[3])
        : "r"(a[0]), "r"(a[1]), "r"(a[2]), "r"(a[3]), "r"(b[0]), "r"(b[1]));
}

__global__ __launch_bounds__(THREADS, 1)
void pw_relu_mma_kernel(const float* __restrict__ x,
                        const float* __restrict__ w,
                        float* __restrict__ out) {
    extern __shared__ char smem[];
    const uint32_t sb = smem_u32(smem);
    const int tid  = threadIdx.x;
    const int lane = tid & 31;
    const int wid  = tid >> 5;
    const int b  = blockIdx.z;
    const int o0 = blockIdx.y * TILE_O;
    const int p0 = blockIdx.x * TILE_P;

    // ---- stage X: natural [eff-k][p] rows; pair rows 2i (relu+), 2i+1 (relu-) ----
    {
        const int pf = tid & 15;               // p = 4*pf .. 4*pf+3
        const int i0 = tid >> 4;               // 0..15
        const float* xb = x + (size_t)b * CIN * HW + p0 + pf * 4;
#pragma unroll
        for (int it = 0; it < 8; it++) {
            const int i = i0 + it * 16;
            float4 v = *(const float4*)(xb + (size_t)i * HW);
            uint32_t pp0 = pack_bf16x2(fmaxf(v.x, 0.f), fmaxf(v.y, 0.f));
            uint32_t pp1 = pack_bf16x2(fmaxf(v.z, 0.f), fmaxf(v.w, 0.f));
            uint32_t pm0 = pack_bf16x2(fmaxf(-v.x, 0.f), fmaxf(-v.y, 0.f));
            uint32_t pm1 = pack_bf16x2(fmaxf(-v.z, 0.f), fmaxf(-v.w, 0.f));
            const uint32_t base = sb + SMEM_B + (uint32_t)(2 * i) * B_STRIDE + pf * 8;
            sts64(base, pp0, pp1);
            sts64(base + B_STRIDE, pm0, pm1);
        }
    }
    // ---- stage W: A rows [o][eff-k], pairs contiguous in k ----
    {
        const int iv = tid & 31;               // i = 4*iv .. 4*iv+3
        const int oo = tid >> 5;               // 0..7
        const float* wb = w + (size_t)(o0 + oo) * CIN + iv * 4;
#pragma unroll
        for (int it = 0; it < 16; it++) {
            const int o = oo + it * 8;
            float4 v = *(const float4*)(wb + (size_t)(it * 8) * CIN);
            uint4 u;
            u.x = pack_bf16x2(fmaxf(v.x, 0.f), fmaxf(-v.x, 0.f));
            u.y = pack_bf16x2(fmaxf(v.y, 0.f), fmaxf(-v.y, 0.f));
            u.z = pack_bf16x2(fmaxf(v.z, 0.f), fmaxf(-v.z, 0.f));
            u.w = pack_bf16x2(fmaxf(v.w, 0.f), fmaxf(-v.w, 0.f));
            sts128(sb + SMEM_A + (uint32_t)o * A_STRIDE + iv * 16, u);
        }
    }
    __syncthreads();

    // ---- mma mainloop: warp tile 32(o) x 32(p) ----
    const int warp_m = wid & 3;    // 4 -> 128 o
    const int warp_n = wid >> 2;   // 2 -> 64 p
    // A ldmatrix lane address: row=(lane&15), col16B=(lane>>4); matrices {m0-7,k0-7},{m8-15,k0-7},{m0-7,k8-15},{m8-15,k8-15}
    const uint32_t aAddr0 = sb + SMEM_A + (uint32_t)(warp_m * 32 + (lane & 15)) * A_STRIDE
                            + (uint32_t)(lane >> 4) * 16;
    // B ldmatrix(trans) lane address: rows are eff-k
    const uint32_t bAddr0 = sb + SMEM_B + (uint32_t)(lane & 15) * B_STRIDE
                            + (uint32_t)(warp_n * 32) * 2;

    float acc[2][4][4];
#pragma unroll
    for (int ms = 0; ms < 2; ms++)
#pragma unroll
        for (int ns = 0; ns < 4; ns++)
#pragma unroll
            for (int j = 0; j < 4; j++) acc[ms][ns][j] = 0.f;

#pragma unroll
    for (int kk = 0; kk < KEFF / 16; kk++) {
        uint32_t a[2][4];
        ldsm_x4(aAddr0 + kk * 32, a[0]);
        ldsm_x4(aAddr0 + 16 * A_STRIDE + kk * 32, a[1]);
        uint32_t bf[4][2];
#pragma unroll
        for (int ns = 0; ns < 4; ns++)
            ldsm_x2_trans(bAddr0 + (uint32_t)kk * (16 * B_STRIDE) + ns * 16, bf[ns]);
#pragma unroll
        for (int ms = 0; ms < 2; ms++)
#pragma unroll
            for (int ns = 0; ns < 4; ns++)
                mma_16816(acc[ms][ns], a[ms], bf[ns]);
    }

    // ---- epilogue: direct coalesced float2 stores from mma fragments ----
    const int r  = lane >> 2;
    const int c2 = (lane & 3) * 2;
    float* ob = out + ((size_t)b * COUT + o0 + warp_m * 32) * HW + p0 + warp_n * 32 + c2;
#pragma unroll
    for (int ms = 0; ms < 2; ms++) {
#pragma unroll
        for (int ns = 0; ns < 4; ns++) {
            float2 v0 = make_float2(acc[ms][ns][0], acc[ms][ns][1]);
            float2 v1 = make_float2(acc[ms][ns][2], acc[ms][ns][3]);
            *(float2*)(ob + (size_t)(ms * 16 + r) * HW + ns * 8)     = v0;
            *(float2*)(ob + (size_t)(ms * 16 + r + 8) * HW + ns * 8) = v1;
        }
    }
}

extern "C" void kernel_launch(void* const* d_in, const int* in_sizes, int n_in,
                              void* d_out, int out_size) {
    const float* x = (const float*)d_in[0];   // (4,128,32,32)
    const float* w = (const float*)d_in[1];   // (256*128,1,1,1)
    float* out = (float*)d_out;               // (4,256,32,32)
    static bool attr_set = false;
    if (!attr_set) {
        cudaFuncSetAttribute(pw_relu_mma_kernel,
                             cudaFuncAttributeMaxDynamicSharedMemorySize, SMEM_TOTAL);
        attr_set = true;
    }
    dim3 grid(HW / TILE_P, COUT / TILE_O, BATCH);   // (16, 2, 4) = 128 CTAs
    pw_relu_mma_kernel<<<grid, THREADS, SMEM_TOTAL>>>(x, w, out);
}